// round 10
// baseline (speedup 1.0000x reference)
#include <cuda_runtime.h>
#include <cuda_bf16.h>
#include <cstdint>

#define TT 16
#define NU 4096
#define EE 128
#define HH 128
#define G4 512
#define LPATH 32
#define NPATH 1024
#define NB 8
#define VOCAB 16384

typedef unsigned long long u64;

__device__ __forceinline__ uint32_t smem_to_u32(const void* p) {
    uint32_t a;
    asm("{ .reg .u64 t; cvta.to.shared.u64 t, %1; cvt.u32.u64 %0, t; }" : "=r"(a) : "l"(p));
    return a;
}
#define LDSM_X4(r, addr) \
    asm volatile("ldmatrix.sync.aligned.m8n8.x4.shared.b16 {%0,%1,%2,%3}, [%4];" \
        : "=r"((r)[0]), "=r"((r)[1]), "=r"((r)[2]), "=r"((r)[3]) : "r"(addr))
__device__ __forceinline__ void mma16816(float* c, const uint32_t* a, uint32_t b0, uint32_t b1) {
    asm volatile("mma.sync.aligned.m16n8k16.row.col.f32.bf16.bf16.f32 "
        "{%0,%1,%2,%3}, {%4,%5,%6,%7}, {%8,%9}, {%0,%1,%2,%3};"
        : "+f"(c[0]), "+f"(c[1]), "+f"(c[2]), "+f"(c[3])
        : "r"(a[0]), "r"(a[1]), "r"(a[2]), "r"(a[3]), "r"(b0), "r"(b1));
}
__device__ __forceinline__ void ffma2(u64& d, u64 a, u64 b) {
    asm("fma.rn.f32x2 %0, %1, %2, %0;" : "+l"(d) : "l"(a), "l"(b));
}
__device__ __forceinline__ u64 dup2(float x) {
    u64 r; asm("mov.b64 %0, {%1, %1};" : "=l"(r) : "f"(x)); return r;
}
__device__ __forceinline__ float2 unpack2(u64 v) {
    float2 f; asm("mov.b64 {%0, %1}, %2;" : "=f"(f.x), "=f"(f.y) : "l"(v)); return f;
}

// ============ device scratch ============
__device__ int   g_tok_len[NU];
__device__ int   g_p_len[NPATH], g_p_fe[NPATH], g_p_off[NPATH], g_p_un[NPATH];
__device__ float g_VTf[VOCAB * G4], g_VTb[VOCAB * G4];
__device__ float g_PTf[NU * G4],    g_PTb[NU * G4];
__device__ float g_lin[TT * NU * EE];
__device__ float g_WhT[4][HH * G4];
__device__ float g_zero[G4];
__device__ __nv_bfloat16 g_emb_h[VOCAB * EE],  g_emb_l[VOCAB * EE];
__device__ __nv_bfloat16 g_Hcat_h[TT * NU * 2 * HH], g_Hcat_l[TT * NU * 2 * HH];
__device__ __nv_bfloat16 g_tf_h[NU * EE], g_tf_l[NU * EE];
__device__ __nv_bfloat16 g_Hp_h[LPATH * NPATH * 2 * HH], g_Hp_l[LPATH * NPATH * 2 * HH];
__device__ __nv_bfloat16 g_Wih[4][G4 * EE], g_Wil[4][G4 * EE];
__device__ __nv_bfloat16 g_W2h[2][EE * 2 * HH], g_W2l[2][EE * 2 * HH];

// ============ setup kernels ============
__global__ void k_tok_len(const int* __restrict__ units) {
    int n = blockIdx.x * blockDim.x + threadIdx.x;
    if (n >= NU) return;
    int len = TT;
    for (int t = 0; t < TT; t++) if (units[t * NU + n] == 0) { len = t; break; }
    g_tok_len[n] = len;
}
__global__ void k_transpose4(const float* __restrict__ W0, const float* __restrict__ W1,
                             const float* __restrict__ W2, const float* __restrict__ W3) {
    int w = blockIdx.y;
    const float* W = (w == 0) ? W0 : (w == 1) ? W1 : (w == 2) ? W2 : W3;
    int idx = blockIdx.x * blockDim.x + threadIdx.x;
    if (idx >= G4 * HH) return;
    int j = idx >> 7, k = idx & 127;
    g_WhT[w][k * G4 + j] = W[idx];
}
__global__ void k_plen(const int* __restrict__ paths,
                       const int* __restrict__ upd, const int* __restrict__ ppd) {
    int p = blockIdx.x * blockDim.x + threadIdx.x;
    if (p >= NPATH) return;
    int dd = NB - 1, cum = 0;
    for (int i = 0; i < NB; i++) { int nx = cum + ppd[i]; if (p >= cum && p < nx) { dd = i; break; } cum = nx; }
    int off = 0;
    for (int i = 0; i < dd; i++) off += upd[i];
    int un = upd[dd];
    int fe = LPATH;
    for (int t = 0; t < LPATH; t++) if (paths[t * NPATH + p] == -1) { fe = t; break; }
    int plen = LPATH;
    for (int t = 0; t < LPATH; t++) {
        bool msk;
        if (t >= fe) msk = true;
        else { int v = paths[t * NPATH + p]; msk = (v < 0) || (v > un); }
        if (msk) { plen = t; break; }
    }
    g_p_len[p] = plen; g_p_fe[p] = fe; g_p_off[p] = off; g_p_un[p] = un;
}

__device__ __forceinline__ void hilo_one(const float* src, __nv_bfloat16* hi,
                                         __nv_bfloat16* lo, int i) {
    float4 v = reinterpret_cast<const float4*>(src)[i];
    __nv_bfloat16 h0 = __float2bfloat16(v.x), h1 = __float2bfloat16(v.y);
    __nv_bfloat16 h2 = __float2bfloat16(v.z), h3 = __float2bfloat16(v.w);
    __nv_bfloat162* H = reinterpret_cast<__nv_bfloat162*>(hi);
    __nv_bfloat162* L = reinterpret_cast<__nv_bfloat162*>(lo);
    H[2 * i] = __nv_bfloat162(h0, h1); H[2 * i + 1] = __nv_bfloat162(h2, h3);
    L[2 * i] = __nv_bfloat162(__float2bfloat16(v.x - __bfloat162float(h0)),
                              __float2bfloat16(v.y - __bfloat162float(h1)));
    L[2 * i + 1] = __nv_bfloat162(__float2bfloat16(v.z - __bfloat162float(h2)),
                                  __float2bfloat16(v.w - __bfloat162float(h3)));
}
struct HiloArgs { const float* s[4]; __nv_bfloat16* h[4]; __nv_bfloat16* l[4]; int n[4]; };
__global__ void k_hilo_multi(HiloArgs a) {
    int seg = blockIdx.y;
    int i = blockIdx.x * blockDim.x + threadIdx.x;
    if (i < a.n[seg]) hilo_one(a.s[seg], a.h[seg], a.l[seg], i);
}

// ============ warp-MMA split-bf16 GEMM (dual-capable via gridDim.z) ============
template <int K>
__global__ __launch_bounds__(256) void k_mm2(
    const __nv_bfloat16* __restrict__ Ah, const __nv_bfloat16* __restrict__ Al,
    const __nv_bfloat16* __restrict__ Bh0, const __nv_bfloat16* __restrict__ Bl0,
    const float* __restrict__ bias0, float* __restrict__ C0,
    const __nv_bfloat16* __restrict__ Bh1, const __nv_bfloat16* __restrict__ Bl1,
    const float* __restrict__ bias1, float* __restrict__ C1, int Ntot)
{
    const __nv_bfloat16* __restrict__ Bh = blockIdx.z ? Bh1 : Bh0;
    const __nv_bfloat16* __restrict__ Bl = blockIdx.z ? Bl1 : Bl0;
    const float* __restrict__ bias = blockIdx.z ? bias1 : bias0;
    float* __restrict__ C = blockIdx.z ? C1 : C0;

    constexpr int LDS = 72;
    extern __shared__ __nv_bfloat16 sm[];
    __nv_bfloat16* sAh = sm;
    __nv_bfloat16* sAl = sAh + 128 * LDS;
    __nv_bfloat16* sBh = sAl + 128 * LDS;
    __nv_bfloat16* sBl = sBh + 128 * LDS;

    const int tid = threadIdx.x, lane = tid & 31, wid = tid >> 5;
    const int m0 = blockIdx.y * 128, n0 = blockIdx.x * 128;
    const int wm = (wid & 3) * 32, wn = (wid >> 2) * 64;
    const int g = lane >> 2, tg = lane & 3;
    const int seg = lane >> 3, i8 = lane & 7;
    const uint32_t sAh_b = smem_to_u32(sAh), sAl_b = smem_to_u32(sAl);
    const uint32_t sBh_b = smem_to_u32(sBh), sBl_b = smem_to_u32(sBl);

    float acc[2][8][4];
#pragma unroll
    for (int im = 0; im < 2; im++)
#pragma unroll
        for (int jn = 0; jn < 8; jn++)
#pragma unroll
            for (int q = 0; q < 4; q++) acc[im][jn][q] = 0.f;

    for (int kc = 0; kc < K; kc += 64) {
        if (kc) __syncthreads();
        {
            const __nv_bfloat16* srcs[4] = {Ah, Al, Bh, Bl};
            __nv_bfloat16* dsts[4] = {sAh, sAl, sBh, sBl};
            const int r0s[4] = {m0, m0, n0, n0};
#pragma unroll
            for (int t = 0; t < 4; t++) {
                for (int v = tid; v < 1024; v += 256) {
                    int row = v >> 3, q = (v & 7) * 8;
                    *reinterpret_cast<uint4*>(dsts[t] + row * LDS + q) =
                        *reinterpret_cast<const uint4*>(srcs[t] + (size_t)(r0s[t] + row) * K + kc + q);
                }
            }
        }
        __syncthreads();
#pragma unroll
        for (int ks = 0; ks < 4; ks++) {
            const int k0 = ks * 16;
            uint32_t ah[2][4], al[2][4];
#pragma unroll
            for (int im = 0; im < 2; im++) {
                int arow = wm + im * 16 + (seg & 1) * 8 + i8;
                int acol = k0 + (seg >> 1) * 8;
                LDSM_X4(ah[im], sAh_b + (uint32_t)(arow * LDS + acol) * 2u);
                LDSM_X4(al[im], sAl_b + (uint32_t)(arow * LDS + acol) * 2u);
            }
#pragma unroll
            for (int ip = 0; ip < 4; ip++) {
                int brow = wn + ip * 16 + (seg >> 1) * 8 + i8;
                int bcol = k0 + (seg & 1) * 8;
                uint32_t bh4[4], bl4[4];
                LDSM_X4(bh4, sBh_b + (uint32_t)(brow * LDS + bcol) * 2u);
                LDSM_X4(bl4, sBl_b + (uint32_t)(brow * LDS + bcol) * 2u);
#pragma unroll
                for (int im = 0; im < 2; im++) {
#pragma unroll
                    for (int hf = 0; hf < 2; hf++) {
                        float* c = acc[im][ip * 2 + hf];
                        mma16816(c, ah[im], bh4[2 * hf], bh4[2 * hf + 1]);
                        mma16816(c, al[im], bh4[2 * hf], bh4[2 * hf + 1]);
                        mma16816(c, ah[im], bl4[2 * hf], bl4[2 * hf + 1]);
                    }
                }
            }
        }
    }
#pragma unroll
    for (int im = 0; im < 2; im++) {
#pragma unroll
        for (int jn = 0; jn < 8; jn++) {
            int col = n0 + wn + jn * 8 + tg * 2;
            float b0v = bias[col], b1v = bias[col + 1];
            int row0 = m0 + wm + im * 16 + g;
            float2 v0 = make_float2(acc[im][jn][0] + b0v, acc[im][jn][1] + b1v);
            float2 v1 = make_float2(acc[im][jn][2] + b0v, acc[im][jn][3] + b1v);
            *reinterpret_cast<float2*>(C + (size_t)row0 * Ntot + col) = v0;
            *reinterpret_cast<float2*>(C + (size_t)(row0 + 8) * Ntot + col) = v1;
        }
    }
}

// ============ persistent BiLSTM (R7 structure; geometry = occupancy fix) ============
__device__ __forceinline__ float sigm(float x) { return 1.f / (1.f + expf(-x)); }

template <int MODE, int TSTEPS, int NSEQ, int ROWS, int THREADS>
__global__ __launch_bounds__(THREADS, 2) void k_lstm(
    const int* __restrict__ idxmat,
    const float* __restrict__ tab_f, const float* __restrict__ tab_b,
    const float* __restrict__ bias_f, const float* __restrict__ bias_b,
    __nv_bfloat16* __restrict__ Hh, __nv_bfloat16* __restrict__ Hl)
{
    constexpr int NW = THREADS / 32, RPT = ROWS / NW;
    constexpr int N4 = 2048 / THREADS;
    extern __shared__ char dsm[];
    float* hs    = reinterpret_cast<float*>(dsm);
    float* wst   = hs + ROWS * HH;
    float* sbias = wst + 2 * 16 * G4;
    int* slen = reinterpret_cast<int*>(sbias + G4);
    int* sfe = slen + ROWS; int* soff = sfe + ROWS; int* sun = soff + ROWS;

    const int dir = blockIdx.y;
    const float* __restrict__ tab = dir ? tab_b : tab_f;
    const float* __restrict__ WhT = g_WhT[2 * MODE + dir];
    const int n0 = blockIdx.x * ROWS;
    const int tid = threadIdx.x, jt = tid & 31, rt = tid >> 5;
    const int e0 = jt * 4, r0 = rt * RPT;

    if (MODE == 1) {
        const float* b = dir ? bias_b : bias_f;
        for (int i = tid; i < G4; i += THREADS) sbias[i] = b[i];
    }
    float c[RPT][4];
#pragma unroll
    for (int r = 0; r < RPT; r++) {
#pragma unroll
        for (int u = 0; u < 4; u++) c[r][u] = 0.f;
        *reinterpret_cast<float4*>(&hs[(r0 + r) * HH + e0]) = make_float4(0.f, 0.f, 0.f, 0.f);
    }
    if (tid < ROWS) {
        int n = n0 + tid;
        slen[tid] = MODE ? g_p_len[n] : g_tok_len[n];
        if (MODE) { sfe[tid] = g_p_fe[n]; soff[tid] = g_p_off[n]; sun[tid] = g_p_un[n]; }
    }
#pragma unroll
    for (int t = 0; t < N4; t++) {
        int i = tid + t * THREADS;
        reinterpret_cast<float4*>(wst)[i] = reinterpret_cast<const float4*>(WhT)[i];
    }
    __syncthreads();

    for (int s = 0; s < TSTEPS; s++) {
        u64 acc64[RPT][8];
#pragma unroll
        for (int r = 0; r < RPT; r++)
#pragma unroll
            for (int j = 0; j < 8; j++) acc64[r][j] = 0ull;

#pragma unroll
        for (int ch = 0; ch < 8; ch++) {
            const float* wcur = wst + (ch & 1) * (16 * G4);
            float* wnxt = wst + ((ch + 1) & 1) * (16 * G4);
            const int nxt = (ch + 1) & 7;
            float4 pre[N4];
#pragma unroll
            for (int t = 0; t < N4; t++)
                pre[t] = reinterpret_cast<const float4*>(WhT)[nxt * 2048 + tid + t * THREADS];

#pragma unroll
            for (int kk = 0; kk < 16; kk++) {
                ulonglong2 wA = *reinterpret_cast<const ulonglong2*>(&wcur[kk * G4 + e0]);
                ulonglong2 wB = *reinterpret_cast<const ulonglong2*>(&wcur[kk * G4 + 128 + e0]);
                ulonglong2 wC = *reinterpret_cast<const ulonglong2*>(&wcur[kk * G4 + 256 + e0]);
                ulonglong2 wD = *reinterpret_cast<const ulonglong2*>(&wcur[kk * G4 + 384 + e0]);
#pragma unroll
                for (int r = 0; r < RPT; r++) {
                    u64 h2 = dup2(hs[(r0 + r) * HH + ch * 16 + kk]);
                    ffma2(acc64[r][0], h2, wA.x); ffma2(acc64[r][1], h2, wA.y);
                    ffma2(acc64[r][2], h2, wB.x); ffma2(acc64[r][3], h2, wB.y);
                    ffma2(acc64[r][4], h2, wC.x); ffma2(acc64[r][5], h2, wC.y);
                    ffma2(acc64[r][6], h2, wD.x); ffma2(acc64[r][7], h2, wD.y);
                }
            }
#pragma unroll
            for (int t = 0; t < N4; t++)
                reinterpret_cast<float4*>(wnxt)[tid + t * THREADS] = pre[t];
            __syncthreads();
        }

        float hnew[RPT][4];
#pragma unroll
        for (int r = 0; r < RPT; r++) {
            float a16[16];
#pragma unroll
            for (int j = 0; j < 8; j++) {
                float2 v = unpack2(acc64[r][j]);
                a16[j * 2] = v.x; a16[j * 2 + 1] = v.y;
            }
            int rr = r0 + r, n = n0 + rr, len = slen[rr];
            int gi = dir ? min(max(len - 1 - s, 0), TSTEPS - 1) : s;
            float gv[16];
            if (MODE == 0) {
                int id = idxmat[(size_t)gi * NSEQ + n];
                const float* grow = tab + (size_t)id * G4;
                float4 a0 = *reinterpret_cast<const float4*>(&grow[e0]);
                float4 a1 = *reinterpret_cast<const float4*>(&grow[128 + e0]);
                float4 a2 = *reinterpret_cast<const float4*>(&grow[256 + e0]);
                float4 a3 = *reinterpret_cast<const float4*>(&grow[384 + e0]);
                gv[0]=a0.x; gv[1]=a0.y; gv[2]=a0.z; gv[3]=a0.w;
                gv[4]=a1.x; gv[5]=a1.y; gv[6]=a1.z; gv[7]=a1.w;
                gv[8]=a2.x; gv[9]=a2.y; gv[10]=a2.z; gv[11]=a2.w;
                gv[12]=a3.x; gv[13]=a3.y; gv[14]=a3.z; gv[15]=a3.w;
            } else {
                int pl = idxmat[(size_t)gi * NSEQ + n];
                bool keep = (gi < sfe[rr]) && (pl >= 0) && (pl < sun[rr]);
                float4 b0 = *reinterpret_cast<const float4*>(&sbias[e0]);
                float4 b1 = *reinterpret_cast<const float4*>(&sbias[128 + e0]);
                float4 b2 = *reinterpret_cast<const float4*>(&sbias[256 + e0]);
                float4 b3 = *reinterpret_cast<const float4*>(&sbias[384 + e0]);
                gv[0]=b0.x; gv[1]=b0.y; gv[2]=b0.z; gv[3]=b0.w;
                gv[4]=b1.x; gv[5]=b1.y; gv[6]=b1.z; gv[7]=b1.w;
                gv[8]=b2.x; gv[9]=b2.y; gv[10]=b2.z; gv[11]=b2.w;
                gv[12]=b3.x; gv[13]=b3.y; gv[14]=b3.z; gv[15]=b3.w;
                if (keep) {
                    int gidx = min(pl + soff[rr], NU - 1);
                    const float* grow = tab + (size_t)gidx * G4;
                    float4 t0 = *reinterpret_cast<const float4*>(&grow[e0]);
                    float4 t1 = *reinterpret_cast<const float4*>(&grow[128 + e0]);
                    float4 t2 = *reinterpret_cast<const float4*>(&grow[256 + e0]);
                    float4 t3 = *reinterpret_cast<const float4*>(&grow[384 + e0]);
                    gv[0]+=t0.x; gv[1]+=t0.y; gv[2]+=t0.z; gv[3]+=t0.w;
                    gv[4]+=t1.x; gv[5]+=t1.y; gv[6]+=t1.z; gv[7]+=t1.w;
                    gv[8]+=t2.x; gv[9]+=t2.y; gv[10]+=t2.z; gv[11]+=t2.w;
                    gv[12]+=t3.x; gv[13]+=t3.y; gv[14]+=t3.z; gv[15]+=t3.w;
                }
            }
#pragma unroll
            for (int u = 0; u < 4; u++) {
                float iv = a16[u]      + gv[u];
                float fv = a16[4 + u]  + gv[4 + u];
                float gg = a16[8 + u]  + gv[8 + u];
                float ov = a16[12 + u] + gv[12 + u];
                float cn = sigm(fv) * c[r][u] + sigm(iv) * tanhf(gg);
                c[r][u] = cn;
                hnew[r][u] = sigm(ov) * tanhf(cn);
            }
            if (s < len) {
                int wi = dir ? (len - 1 - s) : s;
                size_t base = ((size_t)wi * NSEQ + n) * (2 * HH) + dir * HH + e0;
                __nv_bfloat16 hb[4], lb[4];
#pragma unroll
                for (int u = 0; u < 4; u++) {
                    hb[u] = __float2bfloat16(hnew[r][u]);
                    lb[u] = __float2bfloat16(hnew[r][u] - __bfloat162float(hb[u]));
                }
                *reinterpret_cast<uint2*>(Hh + base) = *reinterpret_cast<uint2*>(hb);
                *reinterpret_cast<uint2*>(Hl + base) = *reinterpret_cast<uint2*>(lb);
            } else if (dir == 0) {
                uint2 z = make_uint2(0u, 0u);
                size_t b0 = ((size_t)s * NSEQ + n) * (2 * HH) + e0;
                *reinterpret_cast<uint2*>(Hh + b0) = z;
                *reinterpret_cast<uint2*>(Hl + b0) = z;
                *reinterpret_cast<uint2*>(Hh + b0 + HH) = z;
                *reinterpret_cast<uint2*>(Hl + b0 + HH) = z;
            }
        }
        __syncthreads();
#pragma unroll
        for (int r = 0; r < RPT; r++)
            *reinterpret_cast<float4*>(&hs[(r0 + r) * HH + e0]) =
                make_float4(hnew[r][0], hnew[r][1], hnew[r][2], hnew[r][3]);
        __syncthreads();
    }
}

// ============ attention pooling ============
__global__ void k_attn(const float* __restrict__ ln_g, const float* __restrict__ ln_b,
                       const float* __restrict__ attn_w, const float* __restrict__ attn_bp) {
    int gwarp = (blockIdx.x * blockDim.x + threadIdx.x) >> 5;
    int lane = threadIdx.x & 31;
    if (gwarp >= NU) return;
    int n = gwarp, len = g_tok_len[n];
    float gg[4], bb[4], aw[4];
#pragma unroll
    for (int q = 0; q < 4; q++) {
        int e = lane + 32 * q;
        gg[q] = ln_g[e]; bb[q] = ln_b[e]; aw[q] = attn_w[e];
    }
    float ab = attn_bp[0];
    float sc[TT], smax = -1e30f;
#pragma unroll
    for (int t = 0; t < TT; t++) {
        sc[t] = -1e30f;
        if (t < len) {
            float o[4], lsum = 0.f;
#pragma unroll
            for (int q = 0; q < 4; q++) {
                o[q] = g_lin[((size_t)t * NU + n) * EE + lane + 32 * q];
                lsum += o[q];
            }
#pragma unroll
            for (int off = 16; off; off >>= 1) lsum += __shfl_xor_sync(0xffffffffu, lsum, off);
            float mean = lsum * (1.f / 128.f);
            float vs = 0.f;
#pragma unroll
            for (int q = 0; q < 4; q++) { float d = o[q] - mean; vs += d * d; }
#pragma unroll
            for (int off = 16; off; off >>= 1) vs += __shfl_xor_sync(0xffffffffu, vs, off);
            float inv = rsqrtf(vs * (1.f / 128.f) + 1e-5f);
            float ssum = 0.f;
#pragma unroll
            for (int q = 0; q < 4; q++)
                ssum += tanhf((o[q] - mean) * inv * gg[q] + bb[q]) * aw[q];
#pragma unroll
            for (int off = 16; off; off >>= 1) ssum += __shfl_xor_sync(0xffffffffu, ssum, off);
            sc[t] = ssum + ab;
            smax = fmaxf(smax, sc[t]);
        }
    }
    float den = 0.f, wts[TT];
#pragma unroll
    for (int t = 0; t < TT; t++) {
        wts[t] = (t < len) ? expf(sc[t] - smax) : 0.f;
        den += wts[t];
    }
    float invden = 1.f / den;
    float accq[4] = {0.f, 0.f, 0.f, 0.f};
#pragma unroll
    for (int t = 0; t < TT; t++) {
        if (t < len) {
            float wt = wts[t] * invden;
#pragma unroll
            for (int q = 0; q < 4; q++)
                accq[q] += wt * g_lin[((size_t)t * NU + n) * EE + lane + 32 * q];
        }
    }
#pragma unroll
    for (int q = 0; q < 4; q++) {
        __nv_bfloat16 h = __float2bfloat16(accq[q]);
        __nv_bfloat16 l = __float2bfloat16(accq[q] - __bfloat162float(h));
        g_tf_h[(size_t)n * EE + lane + 32 * q] = h;
        g_tf_l[(size_t)n * EE + lane + 32 * q] = l;
    }
}

// ============ host launcher ============
extern "C" void kernel_launch(void* const* d_in, const int* in_sizes, int n_in,
                              void* d_out, int out_size) {
    const int*   units  = (const int*)d_in[0];
    const int*   paths  = (const int*)d_in[1];
    const int*   upd    = (const int*)d_in[2];
    const int*   ppd    = (const int*)d_in[3];
    const float* emb    = (const float*)d_in[4];
    const float* tl_Wif = (const float*)d_in[5];
    const float* tl_Whf = (const float*)d_in[6];
    const float* tl_bf  = (const float*)d_in[7];
    const float* tl_Wib = (const float*)d_in[8];
    const float* tl_Whb = (const float*)d_in[9];
    const float* tl_bb  = (const float*)d_in[10];
    const float* lin_W  = (const float*)d_in[11];
    const float* lin_b  = (const float*)d_in[12];
    const float* ln_g   = (const float*)d_in[13];
    const float* ln_bv  = (const float*)d_in[14];
    const float* attn_w = (const float*)d_in[15];
    const float* attn_b = (const float*)d_in[16];
    const float* pl_Wif = (const float*)d_in[17];
    const float* pl_Whf = (const float*)d_in[18];
    const float* pl_bf  = (const float*)d_in[19];
    const float* pl_Wib = (const float*)d_in[20];
    const float* pl_Whb = (const float*)d_in[21];
    const float* pl_bb  = (const float*)d_in[22];
    const float* ul_W   = (const float*)d_in[23];
    const float* ul_b   = (const float*)d_in[24];
    float* out = (float*)d_out;

    void *pVTf, *pVTb, *pPTf, *pPTb, *pZero, *pLin;
    cudaGetSymbolAddress(&pVTf, g_VTf);    cudaGetSymbolAddress(&pVTb, g_VTb);
    cudaGetSymbolAddress(&pPTf, g_PTf);    cudaGetSymbolAddress(&pPTb, g_PTb);
    cudaGetSymbolAddress(&pZero, g_zero);  cudaGetSymbolAddress(&pLin, g_lin);
    void *pEh, *pEl, *pHch, *pHcl, *pTfh, *pTfl, *pHph, *pHpl, *pWih, *pWil, *pW2h, *pW2l;
    cudaGetSymbolAddress(&pEh, g_emb_h);   cudaGetSymbolAddress(&pEl, g_emb_l);
    cudaGetSymbolAddress(&pHch, g_Hcat_h); cudaGetSymbolAddress(&pHcl, g_Hcat_l);
    cudaGetSymbolAddress(&pTfh, g_tf_h);   cudaGetSymbolAddress(&pTfl, g_tf_l);
    cudaGetSymbolAddress(&pHph, g_Hp_h);   cudaGetSymbolAddress(&pHpl, g_Hp_l);
    cudaGetSymbolAddress(&pWih, g_Wih);    cudaGetSymbolAddress(&pWil, g_Wil);
    cudaGetSymbolAddress(&pW2h, g_W2h);    cudaGetSymbolAddress(&pW2l, g_W2l);
    __nv_bfloat16* Wih = (__nv_bfloat16*)pWih;  __nv_bfloat16* Wil = (__nv_bfloat16*)pWil;
    __nv_bfloat16* W2h = (__nv_bfloat16*)pW2h;  __nv_bfloat16* W2l = (__nv_bfloat16*)pW2l;

    const int MM_SMEM = 4 * 128 * 72 * 2;
    const int LS_T = 32 * HH * 4 + 2 * 16 * G4 * 4 + G4 * 4 + 4 * 32 * 4;  // 84480
    const int LS_P = 8 * HH * 4 + 2 * 16 * G4 * 4 + G4 * 4 + 4 * 8 * 4;    // 71936
    cudaFuncSetAttribute(k_mm2<128>, cudaFuncAttributeMaxDynamicSharedMemorySize, MM_SMEM);
    cudaFuncSetAttribute(k_mm2<256>, cudaFuncAttributeMaxDynamicSharedMemorySize, MM_SMEM);
    cudaFuncSetAttribute((const void*)k_lstm<0, TT, NU, 32, 256>,
                         cudaFuncAttributeMaxDynamicSharedMemorySize, LS_T + 1024);
    cudaFuncSetAttribute((const void*)k_lstm<1, LPATH, NPATH, 8, 128>,
                         cudaFuncAttributeMaxDynamicSharedMemorySize, LS_P + 1024);

    // launch 0
    k_tok_len<<<NU / 256, 256>>>(units);
    // launch 1
    k_transpose4<<<dim3((G4 * HH + 255) / 256, 4), 256>>>(tl_Whf, tl_Whb, pl_Whf, pl_Whb);
    // launch 2: hilo emb + tl_Wif + tl_Wib (+ lin_W)
    {
        HiloArgs a;
        a.s[0] = emb;    a.h[0] = (__nv_bfloat16*)pEh; a.l[0] = (__nv_bfloat16*)pEl; a.n[0] = VOCAB * EE / 4;
        a.s[1] = tl_Wif; a.h[1] = Wih + 0 * G4 * EE;   a.l[1] = Wil + 0 * G4 * EE;   a.n[1] = G4 * EE / 4;
        a.s[2] = tl_Wib; a.h[2] = Wih + 1 * G4 * EE;   a.l[2] = Wil + 1 * G4 * EE;   a.n[2] = G4 * EE / 4;
        a.s[3] = lin_W;  a.h[3] = W2h;                 a.l[3] = W2l;                 a.n[3] = EE * 256 / 4;
        k_hilo_multi<<<dim3((VOCAB * EE / 4 + 255) / 256, 4), 256>>>(a);
    }
    // launch 3: VT = emb @ Wi^T + b (both dirs, grid.z=2)
    k_mm2<128><<<dim3(4, VOCAB / 128, 2), 256, MM_SMEM>>>(
        (const __nv_bfloat16*)pEh, (const __nv_bfloat16*)pEl,
        Wih + 0 * G4 * EE, Wil + 0 * G4 * EE, tl_bf, (float*)pVTf,
        Wih + 1 * G4 * EE, Wil + 1 * G4 * EE, tl_bb, (float*)pVTb, G4);
    // launch 4 (PROFILED): token BiLSTM
    k_lstm<0, TT, NU, 32, 256><<<dim3(NU / 32, 2), 256, LS_T>>>(
        units, (const float*)pVTf, (const float*)pVTb, nullptr, nullptr,
        (__nv_bfloat16*)pHch, (__nv_bfloat16*)pHcl);
    // launch 5
    k_plen<<<NPATH / 256, 256>>>(paths, upd, ppd);
    // launch 6: hilo pl_Wif/pl_Wib/ul_W
    {
        HiloArgs a;
        a.s[0] = pl_Wif; a.h[0] = Wih + 2 * G4 * EE; a.l[0] = Wil + 2 * G4 * EE; a.n[0] = G4 * EE / 4;
        a.s[1] = pl_Wib; a.h[1] = Wih + 3 * G4 * EE; a.l[1] = Wil + 3 * G4 * EE; a.n[1] = G4 * EE / 4;
        a.s[2] = ul_W;   a.h[2] = W2h + EE * 256;    a.l[2] = W2l + EE * 256;    a.n[2] = EE * 256 / 4;
        a.s[3] = ul_W;   a.h[3] = W2h + EE * 256;    a.l[3] = W2l + EE * 256;    a.n[3] = 0;
        k_hilo_multi<<<dim3((G4 * EE / 4 + 255) / 256, 4), 256>>>(a);
    }
    // launch 7: lin = Hcat @ lin_W^T + lin_b
    k_mm2<256><<<dim3(1, TT * NU / 128, 1), 256, MM_SMEM>>>(
        (const __nv_bfloat16*)pHch, (const __nv_bfloat16*)pHcl,
        W2h, W2l, lin_b, (float*)pLin, W2h, W2l, lin_b, (float*)pLin, EE);
    // launch 8: attention -> tf hi/lo
    k_attn<<<(NU * 32) / 256, 256>>>(ln_g, ln_bv, attn_w, attn_b);
    // launch 9: PT (both dirs, grid.z=2)
    k_mm2<128><<<dim3(4, NU / 128, 2), 256, MM_SMEM>>>(
        (const __nv_bfloat16*)pTfh, (const __nv_bfloat16*)pTfl,
        Wih + 2 * G4 * EE, Wil + 2 * G4 * EE, (const float*)pZero, (float*)pPTf,
        Wih + 3 * G4 * EE, Wil + 3 * G4 * EE, (const float*)pZero, (float*)pPTb, G4);
    // launch 10: path BiLSTM
    k_lstm<1, LPATH, NPATH, 8, 128><<<dim3(NPATH / 8, 2), 128, LS_P>>>(
        paths, (const float*)pPTf, (const float*)pPTb, pl_bf, pl_bb,
        (__nv_bfloat16*)pHph, (__nv_bfloat16*)pHpl);
    // launch 11: out = Hp @ ul_W^T + ul_b
    k_mm2<256><<<dim3(1, LPATH * NPATH / 128, 1), 256, MM_SMEM>>>(
        (const __nv_bfloat16*)pHph, (const __nv_bfloat16*)pHpl,
        W2h + EE * 256, W2l + EE * 256, ul_b, out,
        W2h + EE * 256, W2l + EE * 256, ul_b, out, EE);
}